// round 11
// baseline (speedup 1.0000x reference)
#include <cuda_runtime.h>

#define N_NODES 100000
#define E_EDGES 800000
#define GRID    148
#define TPB     256
#define GSTR    (GRID * TPB)

// Scratch (device globals). NOTE: no cross-execution invariant — the fused
// kernel zeroes its own accumulators in phase 0 of EVERY launch. The kernel
// is a pure function of its input buffers (modulo ~1e-6 atomic float order).
__device__ float g_agg1[N_NODES * 64];
__device__ float g_h   [N_NODES * 128];
__device__ float g_agg2[N_NODES * 128];
__device__ float g_h2  [N_NODES * 128];

// Software grid barrier state. g_bar_gen only ever grows (equality-checked,
// wrap-safe); g_bar_arrive returns to 0 after each barrier completes, so the
// state is self-consistent across any number of launches/replays.
__device__ unsigned g_bar_arrive;
__device__ unsigned g_bar_gen;

__device__ __forceinline__ void grid_barrier() {
    __syncthreads();
    if (threadIdx.x == 0) {
        __threadfence();                                   // release my writes
        unsigned gen = atomicAdd(&g_bar_gen, 0u);          // read gen BEFORE arriving
        unsigned ticket = atomicAdd(&g_bar_arrive, 1u);
        if (ticket == GRID - 1) {
            atomicExch(&g_bar_arrive, 0u);                 // reset before release
            __threadfence();
            atomicAdd(&g_bar_gen, 1u);                     // release all waiters
        } else {
            while (atomicAdd(&g_bar_gen, 0u) == gen) { __nanosleep(64); }
        }
        __threadfence();                                   // acquire others' writes
    }
    __syncthreads();
}

// ---------------------------------------------------------------------------
// Phase helpers (all device functions inside the single fused kernel)
// ---------------------------------------------------------------------------
__device__ __forceinline__ float eluf(float v) {
    return v > 0.f ? v : expm1f(v);
}

template <int F4, bool FEAT_CG>
__device__ void scatter_phase(const float* __restrict__ feat,
                              const int* __restrict__ ei,
                              float* __restrict__ agg, int gtid) {
    const int total = E_EDGES * F4;
    for (int idx = gtid; idx < total; idx += GSTR) {
        int e = idx / F4;
        int c = idx - e * F4;
        int src = __ldg(ei + e);
        int dst = __ldg(ei + E_EDGES + e);
        const float4* sp = ((const float4*)feat) + (long long)src * F4 + c;
        float4 v = FEAT_CG ? __ldcg(sp) : __ldg(sp);
        float* p = agg + ((long long)dst * F4 + c) * 4;
        asm volatile("red.global.add.v4.f32 [%0], {%1,%2,%3,%4};"
                     :: "l"(p), "f"(v.x), "f"(v.y), "f"(v.z), "f"(v.w)
                     : "memory");
    }
}

// out[node,128] = [A_row ; B_row] @ [Wrel ; Wroot]^T + bias, optional ELU.
// A supplies first IN/2 features, B the second IN/2. A_CG/B_CG: bypass L1
// for data produced earlier in this same launch.
template <int IN, bool DO_ELU, bool A_CG, bool B_CG>
__device__ void gemm_phase(const float* __restrict__ A,
                           const float* __restrict__ B,
                           const float* __restrict__ Wrel,
                           const float* __restrict__ Wroot,
                           const float* __restrict__ bias,
                           float* __restrict__ out, float* sm) {
    float* Wt = sm;                  // IN*128 floats (input-major transposed)
    float* st = sm + IN * 128;       // 8 warps * 4 nodes * IN staging
    const int HALF = IN / 2;

    for (int idx = threadIdx.x; idx < IN * 128; idx += TPB) {
        int i = idx % IN;            // input index (fast -> coalesced)
        int j = idx / IN;            // output index
        float w = (i < HALF) ? Wrel[j * HALF + i] : Wroot[j * HALF + (i - HALF)];
        Wt[i * 128 + j] = w;
    }
    __syncthreads();

    const int lane = threadIdx.x & 31;
    const int warp = threadIdx.x >> 5;
    const float4 bias4 = ((const float4*)bias)[lane];
    const float4* Wt4 = (const float4*)Wt;
    float* myst = st + warp * 4 * IN;
    float4* myst4 = (float4*)myst;

    for (int tile = blockIdx.x * 32; tile < N_NODES; tile += GRID * 32) {
        int node0 = tile + warp * 4;
        __syncwarp();
        #pragma unroll
        for (int n = 0; n < 4; n++) {
            int node = node0 + n;
            if (node < N_NODES) {
                #pragma unroll
                for (int c = lane; c < IN / 4; c += 32) {
                    float4 v;
                    if (c < HALF / 4) {
                        const float4* ap = ((const float4*)A) + (long long)node * (HALF / 4) + c;
                        v = A_CG ? __ldcg(ap) : __ldg(ap);
                    } else {
                        const float4* bp = ((const float4*)B) + (long long)node * (HALF / 4) + (c - HALF / 4);
                        v = B_CG ? __ldcg(bp) : __ldg(bp);
                    }
                    myst4[n * (IN / 4) + c] = v;
                }
            }
        }
        __syncwarp();

        float4 a0 = bias4, a1 = bias4, a2 = bias4, a3 = bias4;
        #pragma unroll 8
        for (int i = 0; i < IN; i++) {
            float4 w = Wt4[i * 32 + lane];
            float s0 = myst[0 * IN + i];
            float s1 = myst[1 * IN + i];
            float s2 = myst[2 * IN + i];
            float s3 = myst[3 * IN + i];
            a0.x += w.x * s0; a0.y += w.y * s0; a0.z += w.z * s0; a0.w += w.w * s0;
            a1.x += w.x * s1; a1.y += w.y * s1; a1.z += w.z * s1; a1.w += w.w * s1;
            a2.x += w.x * s2; a2.y += w.y * s2; a2.z += w.z * s2; a2.w += w.w * s2;
            a3.x += w.x * s3; a3.y += w.y * s3; a3.z += w.z * s3; a3.w += w.w * s3;
        }

        float4 accs[4] = {a0, a1, a2, a3};
        #pragma unroll
        for (int n = 0; n < 4; n++) {
            int node = node0 + n;
            if (node < N_NODES) {
                float4 r = accs[n];
                if (DO_ELU) {
                    r.x = eluf(r.x); r.y = eluf(r.y);
                    r.z = eluf(r.z); r.w = eluf(r.w);
                }
                ((float4*)out)[node * 32 + lane] = r;
            }
        }
    }
    __syncthreads();   // block done with this phase's smem before reuse
}

__device__ void fc_phase(const float* __restrict__ h2,
                         const float* __restrict__ Wfc1,
                         const float* __restrict__ bfc1,
                         const float* __restrict__ Wfc2,
                         const float* __restrict__ bfc2,
                         float* __restrict__ out, float* sm, int gtid) {
    float* W1s = sm;            // 20*128
    float* W2s = sm + 2560;     // 20
    float* b1s = sm + 2580;     // 20
    for (int i = threadIdx.x; i < 20 * 128; i += TPB) W1s[i] = Wfc1[i];
    if (threadIdx.x < 20) {
        W2s[threadIdx.x] = Wfc2[threadIdx.x];
        b1s[threadIdx.x] = bfc1[threadIdx.x];
    }
    __syncthreads();
    const float b2 = bfc2[0];

    for (int node = gtid; node < N_NODES; node += GSTR) {
        const float4* r = (const float4*)(h2 + (long long)node * 128);
        float acc[20];
        #pragma unroll
        for (int k = 0; k < 20; k++) acc[k] = b1s[k];
        #pragma unroll 4
        for (int i4 = 0; i4 < 32; i4++) {
            float4 v = __ldcg(r + i4);
            #pragma unroll
            for (int k = 0; k < 20; k++) {
                const float* w = &W1s[k * 128 + i4 * 4];
                acc[k] += v.x * w[0] + v.y * w[1] + v.z * w[2] + v.w * w[3];
            }
        }
        float o = b2;
        #pragma unroll
        for (int k = 0; k < 20; k++) o += fmaxf(acc[k], 0.f) * W2s[k];
        out[node] = o;
    }
}

// ---------------------------------------------------------------------------
// Single fused kernel: the entire network, one launch, pure function of inputs.
// ---------------------------------------------------------------------------
__global__ void __launch_bounds__(TPB, 1)
fused_gcn(const float* __restrict__ x, const int* __restrict__ ei,
          const float* __restrict__ W1_rel, const float* __restrict__ b1,
          const float* __restrict__ W1_root,
          const float* __restrict__ W2_rel, const float* __restrict__ b2,
          const float* __restrict__ W2_root,
          const float* __restrict__ Wfc1, const float* __restrict__ bfc1,
          const float* __restrict__ Wfc2, const float* __restrict__ bfc2,
          float* __restrict__ out) {
    extern __shared__ float sm[];
    const int gtid = blockIdx.x * TPB + threadIdx.x;

    // Phase 0: zero accumulators (self-contained — no cross-launch state)
    {
        const float4 z = make_float4(0.f, 0.f, 0.f, 0.f);
        float4* a1 = (float4*)g_agg1;
        float4* a2 = (float4*)g_agg2;
        for (int i = gtid; i < N_NODES * 64 / 4;  i += GSTR) a1[i] = z;
        for (int i = gtid; i < N_NODES * 128 / 4; i += GSTR) a2[i] = z;
    }
    grid_barrier();

    // Phase 1: agg1[dst] += x[src]
    scatter_phase<16, false>(x, ei, g_agg1, gtid);
    grid_barrier();

    // Phase 2: h = elu(agg1 @ W1_rel^T + b1 + x @ W1_root^T)
    gemm_phase<128, true, true, false>(g_agg1, x, W1_rel, W1_root, b1, g_h, sm);
    grid_barrier();

    // Phase 3: agg2[dst] += h[src]
    scatter_phase<32, true>(g_h, ei, g_agg2, gtid);
    grid_barrier();

    // Phase 4: h2 = agg2 @ W2_rel^T + b2 + h @ W2_root^T
    gemm_phase<256, false, true, true>(g_agg2, g_h, W2_rel, W2_root, b2, g_h2, sm);
    grid_barrier();

    // Phase 5: out = relu(h2 @ Wfc1^T + bfc1) @ Wfc2^T + bfc2
    fc_phase(g_h2, Wfc1, bfc1, Wfc2, bfc2, out, sm, gtid);
}

// ---------------------------------------------------------------------------
extern "C" void kernel_launch(void* const* d_in, const int* in_sizes, int n_in,
                              void* d_out, int out_size) {
    const float* x       = (const float*)d_in[0];
    const int*   ei      = (const int*)d_in[1];
    const float* W1_rel  = (const float*)d_in[2];
    const float* b1      = (const float*)d_in[3];
    const float* W1_root = (const float*)d_in[4];
    const float* W2_rel  = (const float*)d_in[5];
    const float* b2      = (const float*)d_in[6];
    const float* W2_root = (const float*)d_in[7];
    const float* Wfc1    = (const float*)d_in[8];
    const float* bfc1    = (const float*)d_in[9];
    const float* Wfc2    = (const float*)d_in[10];
    const float* bfc2    = (const float*)d_in[11];
    float* out = (float*)d_out;

    // smem: max over phases = gemm<256>: (256*128 + 8*4*256) floats = 163840 B
    const int smem = (256 * 128 + 8 * 4 * 256) * 4;
    cudaFuncSetAttribute(fused_gcn,
                         cudaFuncAttributeMaxDynamicSharedMemorySize, smem);

    fused_gcn<<<GRID, TPB, smem>>>(x, ei, W1_rel, b1, W1_root,
                                   W2_rel, b2, W2_root,
                                   Wfc1, bfc1, Wfc2, bfc2, out);
}

// round 12
// speedup vs baseline: 1.3376x; 1.3376x over previous
#include <cuda_runtime.h>

#define N_NODES 100000
#define E_EDGES 800000
#define GRID    148
#define TPB     512
#define NWARP   (TPB / 32)
#define NODES_PER_BLK (NWARP * 4)
#define GSTR    (GRID * TPB)

// Scratch (device globals). No cross-execution invariant — the fused kernel
// zeroes its own accumulators in phase 0 of EVERY launch; pure function of
// its input buffers (modulo ~1e-6 atomic float ordering).
__device__ float g_agg1[N_NODES * 64];
__device__ float g_h   [N_NODES * 128];
__device__ float g_agg2[N_NODES * 128];
__device__ float g_h2  [N_NODES * 128];

// Software grid barrier (grid == #SMs, 1 CTA/SM -> all co-resident).
__device__ unsigned g_bar_arrive;
__device__ unsigned g_bar_gen;

__device__ __forceinline__ void grid_barrier() {
    __syncthreads();
    if (threadIdx.x == 0) {
        __threadfence();
        unsigned gen = atomicAdd(&g_bar_gen, 0u);
        unsigned ticket = atomicAdd(&g_bar_arrive, 1u);
        if (ticket == GRID - 1) {
            atomicExch(&g_bar_arrive, 0u);
            __threadfence();
            atomicAdd(&g_bar_gen, 1u);
        } else {
            while (atomicAdd(&g_bar_gen, 0u) == gen) { __nanosleep(64); }
        }
        __threadfence();
    }
    __syncthreads();
}

__device__ __forceinline__ float eluf(float v) {
    return v > 0.f ? v : expm1f(v);
}

// ---------------------------------------------------------------------------
// Scatter-add phase: agg[dst] += feat[src] (F4 float4 lanes per edge)
// ---------------------------------------------------------------------------
template <int F4, bool FEAT_CG>
__device__ void scatter_phase(const float* __restrict__ feat,
                              const int* __restrict__ ei,
                              float* __restrict__ agg, int gtid) {
    const int total = E_EDGES * F4;
    for (int idx = gtid; idx < total; idx += GSTR) {
        int e = idx / F4;
        int c = idx - e * F4;
        int src = __ldg(ei + e);
        int dst = __ldg(ei + E_EDGES + e);
        const float4* sp = ((const float4*)feat) + (long long)src * F4 + c;
        float4 v = FEAT_CG ? __ldcg(sp) : __ldg(sp);
        float* p = agg + ((long long)dst * F4 + c) * 4;
        asm volatile("red.global.add.v4.f32 [%0], {%1,%2,%3,%4};"
                     :: "l"(p), "f"(v.x), "f"(v.y), "f"(v.z), "f"(v.w)
                     : "memory");
    }
}

// ---------------------------------------------------------------------------
// GEMM phase: out[node,128] = [A_row ; B_row] @ [Wrel ; Wroot]^T + bias.
// 16 warps; warp processes 4 nodes; thread holds float4 accum per node.
// ---------------------------------------------------------------------------
template <int IN, bool DO_ELU, bool A_CG, bool B_CG>
__device__ void gemm_phase(const float* __restrict__ A,
                           const float* __restrict__ B,
                           const float* __restrict__ Wrel,
                           const float* __restrict__ Wroot,
                           const float* __restrict__ bias,
                           float* __restrict__ out, float* sm) {
    float* Wt = sm;                  // IN*128 floats (input-major transposed)
    float* st = sm + IN * 128;       // NWARP warps * 4 nodes * IN staging
    const int HALF = IN / 2;

    for (int idx = threadIdx.x; idx < IN * 128; idx += TPB) {
        int i = idx % IN;            // input index (fast -> coalesced)
        int j = idx / IN;            // output index
        float w = (i < HALF) ? Wrel[j * HALF + i] : Wroot[j * HALF + (i - HALF)];
        Wt[i * 128 + j] = w;
    }
    __syncthreads();

    const int lane = threadIdx.x & 31;
    const int warp = threadIdx.x >> 5;
    const float4 bias4 = ((const float4*)bias)[lane];
    const float4* Wt4 = (const float4*)Wt;
    float* myst = st + warp * 4 * IN;
    float4* myst4 = (float4*)myst;

    for (int tile = blockIdx.x * NODES_PER_BLK; tile < N_NODES;
         tile += GRID * NODES_PER_BLK) {
        int node0 = tile + warp * 4;
        __syncwarp();
        #pragma unroll
        for (int n = 0; n < 4; n++) {
            int node = node0 + n;
            if (node < N_NODES) {
                #pragma unroll
                for (int c = lane; c < IN / 4; c += 32) {
                    float4 v;
                    if (c < HALF / 4) {
                        const float4* ap = ((const float4*)A) + (long long)node * (HALF / 4) + c;
                        v = A_CG ? __ldcg(ap) : __ldg(ap);
                    } else {
                        const float4* bp = ((const float4*)B) + (long long)node * (HALF / 4) + (c - HALF / 4);
                        v = B_CG ? __ldcg(bp) : __ldg(bp);
                    }
                    myst4[n * (IN / 4) + c] = v;
                }
            }
        }
        __syncwarp();

        float4 a0 = bias4, a1 = bias4, a2 = bias4, a3 = bias4;
        #pragma unroll 8
        for (int i = 0; i < IN; i++) {
            float4 w = Wt4[i * 32 + lane];
            float s0 = myst[0 * IN + i];
            float s1 = myst[1 * IN + i];
            float s2 = myst[2 * IN + i];
            float s3 = myst[3 * IN + i];
            a0.x += w.x * s0; a0.y += w.y * s0; a0.z += w.z * s0; a0.w += w.w * s0;
            a1.x += w.x * s1; a1.y += w.y * s1; a1.z += w.z * s1; a1.w += w.w * s1;
            a2.x += w.x * s2; a2.y += w.y * s2; a2.z += w.z * s2; a2.w += w.w * s2;
            a3.x += w.x * s3; a3.y += w.y * s3; a3.z += w.z * s3; a3.w += w.w * s3;
        }

        float4 accs[4] = {a0, a1, a2, a3};
        #pragma unroll
        for (int n = 0; n < 4; n++) {
            int node = node0 + n;
            if (node < N_NODES) {
                float4 r = accs[n];
                if (DO_ELU) {
                    r.x = eluf(r.x); r.y = eluf(r.y);
                    r.z = eluf(r.z); r.w = eluf(r.w);
                }
                ((float4*)out)[node * 32 + lane] = r;
            }
        }
    }
    __syncthreads();   // block done with this phase's smem before reuse
}

// ---------------------------------------------------------------------------
// FC head phase: out[n] = relu(h2[n] @ Wfc1^T + b1) @ Wfc2^T + b2
// ---------------------------------------------------------------------------
__device__ void fc_phase(const float* __restrict__ h2,
                         const float* __restrict__ Wfc1,
                         const float* __restrict__ bfc1,
                         const float* __restrict__ Wfc2,
                         const float* __restrict__ bfc2,
                         float* __restrict__ out, float* sm, int gtid) {
    float* W1s = sm;            // 20*128
    float* W2s = sm + 2560;     // 20
    float* b1s = sm + 2580;     // 20
    for (int i = threadIdx.x; i < 20 * 128; i += TPB) W1s[i] = Wfc1[i];
    if (threadIdx.x < 20) {
        W2s[threadIdx.x] = Wfc2[threadIdx.x];
        b1s[threadIdx.x] = bfc1[threadIdx.x];
    }
    __syncthreads();
    const float b2 = bfc2[0];

    for (int node = gtid; node < N_NODES; node += GSTR) {
        const float4* r = (const float4*)(h2 + (long long)node * 128);
        float acc[20];
        #pragma unroll
        for (int k = 0; k < 20; k++) acc[k] = b1s[k];
        #pragma unroll 4
        for (int i4 = 0; i4 < 32; i4++) {
            float4 v = __ldcg(r + i4);
            #pragma unroll
            for (int k = 0; k < 20; k++) {
                const float* w = &W1s[k * 128 + i4 * 4];
                acc[k] += v.x * w[0] + v.y * w[1] + v.z * w[2] + v.w * w[3];
            }
        }
        float o = b2;
        #pragma unroll
        for (int k = 0; k < 20; k++) o += fmaxf(acc[k], 0.f) * W2s[k];
        out[node] = o;
    }
}

// ---------------------------------------------------------------------------
// Single fused kernel: the entire network, one launch, pure function of inputs.
// ---------------------------------------------------------------------------
__global__ void __launch_bounds__(TPB, 1)
fused_gcn(const float* __restrict__ x, const int* __restrict__ ei,
          const float* __restrict__ W1_rel, const float* __restrict__ b1,
          const float* __restrict__ W1_root,
          const float* __restrict__ W2_rel, const float* __restrict__ b2,
          const float* __restrict__ W2_root,
          const float* __restrict__ Wfc1, const float* __restrict__ bfc1,
          const float* __restrict__ Wfc2, const float* __restrict__ bfc2,
          float* __restrict__ out) {
    extern __shared__ float sm[];
    const int gtid = blockIdx.x * TPB + threadIdx.x;

    // Phase 0: zero accumulators (self-contained, L2-write bound, ~10µs)
    {
        const float4 z = make_float4(0.f, 0.f, 0.f, 0.f);
        float4* a1 = (float4*)g_agg1;
        float4* a2 = (float4*)g_agg2;
        for (int i = gtid; i < N_NODES * 64 / 4;  i += GSTR) a1[i] = z;
        for (int i = gtid; i < N_NODES * 128 / 4; i += GSTR) a2[i] = z;
    }
    grid_barrier();

    // Phase 1: agg1[dst] += x[src]
    scatter_phase<16, false>(x, ei, g_agg1, gtid);
    grid_barrier();

    // Phase 2: h = elu(agg1 @ W1_rel^T + b1 + x @ W1_root^T)
    gemm_phase<128, true, true, false>(g_agg1, x, W1_rel, W1_root, b1, g_h, sm);
    grid_barrier();

    // Phase 3: agg2[dst] += h[src]
    scatter_phase<32, true>(g_h, ei, g_agg2, gtid);
    grid_barrier();

    // Phase 4: h2 = agg2 @ W2_rel^T + b2 + h @ W2_root^T
    gemm_phase<256, false, true, true>(g_agg2, g_h, W2_rel, W2_root, b2, g_h2, sm);
    grid_barrier();

    // Phase 5: out = relu(h2 @ Wfc1^T + bfc1) @ Wfc2^T + bfc2
    fc_phase(g_h2, Wfc1, bfc1, Wfc2, bfc2, out, sm, gtid);
}

// ---------------------------------------------------------------------------
extern "C" void kernel_launch(void* const* d_in, const int* in_sizes, int n_in,
                              void* d_out, int out_size) {
    const float* x       = (const float*)d_in[0];
    const int*   ei      = (const int*)d_in[1];
    const float* W1_rel  = (const float*)d_in[2];
    const float* b1      = (const float*)d_in[3];
    const float* W1_root = (const float*)d_in[4];
    const float* W2_rel  = (const float*)d_in[5];
    const float* b2      = (const float*)d_in[6];
    const float* W2_root = (const float*)d_in[7];
    const float* Wfc1    = (const float*)d_in[8];
    const float* bfc1    = (const float*)d_in[9];
    const float* Wfc2    = (const float*)d_in[10];
    const float* bfc2    = (const float*)d_in[11];
    float* out = (float*)d_out;

    // smem: max over phases = gemm<256>: 256*128 + NWARP*4*256 floats = 192KB
    const int smem = (256 * 128 + NWARP * 4 * 256) * 4;
    cudaFuncSetAttribute(fused_gcn,
                         cudaFuncAttributeMaxDynamicSharedMemorySize, smem);

    fused_gcn<<<GRID, TPB, smem>>>(x, ei, W1_rel, b1, W1_root,
                                   W2_rel, b2, W2_root,
                                   Wfc1, bfc1, Wfc2, bfc2, out);
}

// round 13
// speedup vs baseline: 1.5908x; 1.1893x over previous
#include <cuda_runtime.h>
#include <cstdint>

#define N_NODES 100000
#define E_EDGES 800000
#define GRID    148
#define TPB     512
#define NWARP   (TPB / 32)
#define GSTR    (GRID * TPB)

// Scratch (device globals). The fused kernel zeroes its own accumulators in
// phase 0 of EVERY launch; pure function of inputs (mod atomic fp ordering).
__device__ float g_agg1[N_NODES * 64];
__device__ float g_h   [N_NODES * 128];
__device__ float g_agg2[N_NODES * 128];
__device__ float g_h2  [N_NODES * 128];

// Software grid barrier (grid == #SMs, 1 CTA/SM -> all co-resident).
__device__ unsigned g_bar_arrive;
__device__ unsigned g_bar_gen;

__device__ __forceinline__ void grid_barrier() {
    __syncthreads();
    if (threadIdx.x == 0) {
        __threadfence();
        unsigned gen = atomicAdd(&g_bar_gen, 0u);
        unsigned ticket = atomicAdd(&g_bar_arrive, 1u);
        if (ticket == GRID - 1) {
            atomicExch(&g_bar_arrive, 0u);
            __threadfence();
            atomicAdd(&g_bar_gen, 1u);
        } else {
            while (atomicAdd(&g_bar_gen, 0u) == gen) { __nanosleep(64); }
        }
        __threadfence();
    }
    __syncthreads();
}

__device__ __forceinline__ float eluf(float v) {
    return v > 0.f ? v : expm1f(v);
}

__device__ __forceinline__ uint32_t f2tf32(float f) {
    uint32_t u;
    asm("cvt.rna.tf32.f32 %0, %1;" : "=r"(u) : "f"(f));
    return u;
}

__device__ __forceinline__ void mma_tf32(float c[4], uint32_t a0, uint32_t a1,
                                         uint32_t a2, uint32_t a3,
                                         uint32_t b0, uint32_t b1) {
    asm volatile(
        "mma.sync.aligned.m16n8k8.row.col.f32.tf32.tf32.f32 "
        "{%0,%1,%2,%3}, {%4,%5,%6,%7}, {%8,%9}, {%0,%1,%2,%3};\n"
        : "+f"(c[0]), "+f"(c[1]), "+f"(c[2]), "+f"(c[3])
        : "r"(a0), "r"(a1), "r"(a2), "r"(a3), "r"(b0), "r"(b1));
}

// ---------------------------------------------------------------------------
// Scatter-add phase: agg[dst] += feat[src] (F4 float4 lanes per edge)
// ---------------------------------------------------------------------------
template <int F4, bool FEAT_CG>
__device__ void scatter_phase(const float* __restrict__ feat,
                              const int* __restrict__ ei,
                              float* __restrict__ agg, int gtid) {
    const int total = E_EDGES * F4;
    for (int idx = gtid; idx < total; idx += GSTR) {
        int e = idx / F4;
        int c = idx - e * F4;
        int src = __ldg(ei + e);
        int dst = __ldg(ei + E_EDGES + e);
        const float4* sp = ((const float4*)feat) + (long long)src * F4 + c;
        float4 v = FEAT_CG ? __ldcg(sp) : __ldg(sp);
        float* p = agg + ((long long)dst * F4 + c) * 4;
        asm volatile("red.global.add.v4.f32 [%0], {%1,%2,%3,%4};"
                     :: "l"(p), "f"(v.x), "f"(v.y), "f"(v.z), "f"(v.w)
                     : "memory");
    }
}

// ---------------------------------------------------------------------------
// TF32 tensor-core GEMM phase:
//   out[node,128] = [A_row ; B_row] @ [Wrel ; Wroot]^T + bias  (opt. ELU)
// Tile = 64 nodes x 128 outs; 16 warps in 4x4 grid of m16n32 warp-tiles.
// Weights tf32 in smem [K][136] (pad 8 -> conflict-free B frags);
// activations staged tf32 [64][K+4] (pad 4 -> conflict-free A frags).
// ---------------------------------------------------------------------------
template <int K, bool DO_ELU, bool A_CG, bool B_CG>
__device__ void gemm_mma_phase(const float* __restrict__ A,
                               const float* __restrict__ B,
                               const float* __restrict__ Wrel,
                               const float* __restrict__ Wroot,
                               const float* __restrict__ bias,
                               float* __restrict__ out, float* sm) {
    constexpr int HALF = K / 2;
    constexpr int WROW = 136;       // padded weight row (floats)
    constexpr int SROW = K + 4;     // padded staging row (floats)
    uint32_t* Wt = (uint32_t*)sm;                // [K][WROW] tf32
    uint32_t* S  = (uint32_t*)(sm + K * WROW);   // [64][SROW] tf32

    // Fill weights (tf32-rounded). Wt[k][n], n = output index 0..127.
    for (int idx = threadIdx.x; idx < (K / 4) * 128; idx += TPB) {
        int i4 = idx % (K / 4);
        int j  = idx / (K / 4);
        int k0 = i4 * 4;
        float4 v = (k0 < HALF)
            ? *(const float4*)(Wrel  + j * HALF + k0)
            : *(const float4*)(Wroot + j * HALF + (k0 - HALF));
        Wt[(k0 + 0) * WROW + j] = f2tf32(v.x);
        Wt[(k0 + 1) * WROW + j] = f2tf32(v.y);
        Wt[(k0 + 2) * WROW + j] = f2tf32(v.z);
        Wt[(k0 + 3) * WROW + j] = f2tf32(v.w);
    }

    const int lane = threadIdx.x & 31;
    const int warp = threadIdx.x >> 5;
    const int mw = warp >> 2;       // 0..3 : node-row group
    const int nw = warp & 3;        // 0..3 : output-col group
    const int g  = lane >> 2;       // groupID 0..7
    const int tg = lane & 3;        // threadID_in_group 0..3

    for (int tile = blockIdx.x * 64; tile < N_NODES; tile += GRID * 64) {
        __syncthreads();   // prior iter's mma reads done; weights ready (1st)
        // Stage 64 node rows, tf32-rounded: S[nl][k]
        for (int idx = threadIdx.x; idx < 64 * (K / 4); idx += TPB) {
            int k4 = idx % (K / 4);
            int nl = idx / (K / 4);
            int node = tile + nl;
            float4 v = make_float4(0.f, 0.f, 0.f, 0.f);
            if (node < N_NODES) {
                if (k4 < HALF / 4) {
                    const float4* ap = ((const float4*)A) + (long long)node * (HALF / 4) + k4;
                    v = A_CG ? __ldcg(ap) : __ldg(ap);
                } else {
                    const float4* bp = ((const float4*)B) + (long long)node * (HALF / 4) + (k4 - HALF / 4);
                    v = B_CG ? __ldcg(bp) : __ldg(bp);
                }
            }
            uint4 t;
            t.x = f2tf32(v.x); t.y = f2tf32(v.y);
            t.z = f2tf32(v.z); t.w = f2tf32(v.w);
            *(uint4*)&S[nl * SROW + k4 * 4] = t;
        }
        __syncthreads();

        float c[4][4] = {};
        const int arow0 = (mw * 16 + g) * SROW;
        const int arow8 = arow0 + 8 * SROW;
        #pragma unroll 4
        for (int kk = 0; kk < K; kk += 8) {
            uint32_t a0 = S[arow0 + kk + tg];
            uint32_t a1 = S[arow8 + kk + tg];
            uint32_t a2 = S[arow0 + kk + tg + 4];
            uint32_t a3 = S[arow8 + kk + tg + 4];
            #pragma unroll
            for (int j = 0; j < 4; j++) {
                int n0 = nw * 32 + j * 8 + g;
                uint32_t b0 = Wt[(kk + tg) * WROW + n0];
                uint32_t b1 = Wt[(kk + 4 + tg) * WROW + n0];
                mma_tf32(c[j], a0, a1, a2, a3, b0, b1);
            }
        }

        // Epilogue: bias + (elu) + store float2 pairs
        int r0 = tile + mw * 16 + g;
        int r1 = r0 + 8;
        #pragma unroll
        for (int j = 0; j < 4; j++) {
            int col = nw * 32 + j * 8 + tg * 2;
            float bx = __ldg(bias + col);
            float by = __ldg(bias + col + 1);
            if (r0 < N_NODES) {
                float ox = c[j][0] + bx, oy = c[j][1] + by;
                if (DO_ELU) { ox = eluf(ox); oy = eluf(oy); }
                *(float2*)&out[(long long)r0 * 128 + col] = make_float2(ox, oy);
            }
            if (r1 < N_NODES) {
                float ox = c[j][2] + bx, oy = c[j][3] + by;
                if (DO_ELU) { ox = eluf(ox); oy = eluf(oy); }
                *(float2*)&out[(long long)r1 * 128 + col] = make_float2(ox, oy);
            }
        }
    }
    __syncthreads();
}

// ---------------------------------------------------------------------------
// FC head phase: out[n] = relu(h2[n] @ Wfc1^T + b1) @ Wfc2^T + b2
// ---------------------------------------------------------------------------
__device__ void fc_phase(const float* __restrict__ h2,
                         const float* __restrict__ Wfc1,
                         const float* __restrict__ bfc1,
                         const float* __restrict__ Wfc2,
                         const float* __restrict__ bfc2,
                         float* __restrict__ out, float* sm, int gtid) {
    float* W1s = sm;            // 20*128
    float* W2s = sm + 2560;     // 20
    float* b1s = sm + 2580;     // 20
    for (int i = threadIdx.x; i < 20 * 128; i += TPB) W1s[i] = Wfc1[i];
    if (threadIdx.x < 20) {
        W2s[threadIdx.x] = Wfc2[threadIdx.x];
        b1s[threadIdx.x] = bfc1[threadIdx.x];
    }
    __syncthreads();
    const float b2 = bfc2[0];

    for (int node = gtid; node < N_NODES; node += GSTR) {
        const float4* r = (const float4*)(h2 + (long long)node * 128);
        float acc[20];
        #pragma unroll
        for (int k = 0; k < 20; k++) acc[k] = b1s[k];
        #pragma unroll 4
        for (int i4 = 0; i4 < 32; i4++) {
            float4 v = __ldcg(r + i4);
            #pragma unroll
            for (int k = 0; k < 20; k++) {
                const float* w = &W1s[k * 128 + i4 * 4];
                acc[k] += v.x * w[0] + v.y * w[1] + v.z * w[2] + v.w * w[3];
            }
        }
        float o = b2;
        #pragma unroll
        for (int k = 0; k < 20; k++) o += fmaxf(acc[k], 0.f) * W2s[k];
        out[node] = o;
    }
}

// ---------------------------------------------------------------------------
// Single fused kernel: the entire network, one launch, pure function of inputs.
// ---------------------------------------------------------------------------
__global__ void __launch_bounds__(TPB, 1)
fused_gcn(const float* __restrict__ x, const int* __restrict__ ei,
          const float* __restrict__ W1_rel, const float* __restrict__ b1,
          const float* __restrict__ W1_root,
          const float* __restrict__ W2_rel, const float* __restrict__ b2,
          const float* __restrict__ W2_root,
          const float* __restrict__ Wfc1, const float* __restrict__ bfc1,
          const float* __restrict__ Wfc2, const float* __restrict__ bfc2,
          float* __restrict__ out) {
    extern __shared__ float sm[];
    const int gtid = blockIdx.x * TPB + threadIdx.x;

    // Phase 0: zero accumulators
    {
        const float4 z = make_float4(0.f, 0.f, 0.f, 0.f);
        float4* a1 = (float4*)g_agg1;
        float4* a2 = (float4*)g_agg2;
        for (int i = gtid; i < N_NODES * 64 / 4;  i += GSTR) a1[i] = z;
        for (int i = gtid; i < N_NODES * 128 / 4; i += GSTR) a2[i] = z;
    }
    grid_barrier();

    // Phase 1: agg1[dst] += x[src]
    scatter_phase<16, false>(x, ei, g_agg1, gtid);
    grid_barrier();

    // Phase 2: h = elu(agg1 @ W1_rel^T + b1 + x @ W1_root^T)  [TF32 mma]
    gemm_mma_phase<128, true, true, false>(g_agg1, x, W1_rel, W1_root, b1, g_h, sm);
    grid_barrier();

    // Phase 3: agg2[dst] += h[src]
    scatter_phase<32, true>(g_h, ei, g_agg2, gtid);
    grid_barrier();

    // Phase 4: h2 = agg2 @ W2_rel^T + b2 + h @ W2_root^T  [TF32 mma]
    gemm_mma_phase<256, false, true, true>(g_agg2, g_h, W2_rel, W2_root, b2, g_h2, sm);
    grid_barrier();

    // Phase 5: out = relu(h2 @ Wfc1^T + bfc1) @ Wfc2^T + bfc2
    fc_phase(g_h2, Wfc1, bfc1, Wfc2, bfc2, out, sm, gtid);
}

// ---------------------------------------------------------------------------
extern "C" void kernel_launch(void* const* d_in, const int* in_sizes, int n_in,
                              void* d_out, int out_size) {
    const float* x       = (const float*)d_in[0];
    const int*   ei      = (const int*)d_in[1];
    const float* W1_rel  = (const float*)d_in[2];
    const float* b1      = (const float*)d_in[3];
    const float* W1_root = (const float*)d_in[4];
    const float* W2_rel  = (const float*)d_in[5];
    const float* b2      = (const float*)d_in[6];
    const float* W2_root = (const float*)d_in[7];
    const float* Wfc1    = (const float*)d_in[8];
    const float* bfc1    = (const float*)d_in[9];
    const float* Wfc2    = (const float*)d_in[10];
    const float* bfc2    = (const float*)d_in[11];
    float* out = (float*)d_out;

    // smem: max over phases = K=256 gemm: 256*136 + 64*260 floats = 205824 B
    const int smem = (256 * 136 + 64 * 260) * 4;
    cudaFuncSetAttribute(fused_gcn,
                         cudaFuncAttributeMaxDynamicSharedMemorySize, smem);

    fused_gcn<<<GRID, TPB, smem>>>(x, ei, W1_rel, b1, W1_root,
                                   W2_rel, b2, W2_root,
                                   Wfc1, bfc1, Wfc2, bfc2, out);
}

// round 14
// speedup vs baseline: 1.9377x; 1.2181x over previous
#include <cuda_runtime.h>
#include <cstdint>

#define N_NODES 100000
#define E_EDGES 800000
#define GRID    148
#define TPB     512
#define NWARP   (TPB / 32)
#define GSTR    (GRID * TPB)
#define TOTWARPS (GRID * NWARP)

// Scratch (device globals). The fused kernel zeroes its own accumulators in
// phase 0 of EVERY launch; pure function of inputs (mod atomic fp ordering).
__device__ float g_agg1[N_NODES * 64];
__device__ float g_h   [N_NODES * 128];
__device__ float g_agg2[N_NODES * 128];
__device__ float g_h2  [N_NODES * 128];

// Software grid barrier (grid == #SMs, 1 CTA/SM -> all co-resident).
__device__ unsigned g_bar_arrive;
__device__ unsigned g_bar_gen;

__device__ __forceinline__ void grid_barrier() {
    __syncthreads();
    if (threadIdx.x == 0) {
        __threadfence();
        unsigned gen = atomicAdd(&g_bar_gen, 0u);
        unsigned ticket = atomicAdd(&g_bar_arrive, 1u);
        if (ticket == GRID - 1) {
            atomicExch(&g_bar_arrive, 0u);
            __threadfence();
            atomicAdd(&g_bar_gen, 1u);
        } else {
            while (atomicAdd(&g_bar_gen, 0u) == gen) { __nanosleep(64); }
        }
        __threadfence();
    }
    __syncthreads();
}

__device__ __forceinline__ float eluf(float v) {
    return v > 0.f ? v : expm1f(v);
}

__device__ __forceinline__ uint32_t f2tf32(float f) {
    uint32_t u;
    asm("cvt.rna.tf32.f32 %0, %1;" : "=r"(u) : "f"(f));
    return u;
}

__device__ __forceinline__ void mma_tf32(float c[4], uint32_t a0, uint32_t a1,
                                         uint32_t a2, uint32_t a3,
                                         uint32_t b0, uint32_t b1) {
    asm volatile(
        "mma.sync.aligned.m16n8k8.row.col.f32.tf32.tf32.f32 "
        "{%0,%1,%2,%3}, {%4,%5,%6,%7}, {%8,%9}, {%0,%1,%2,%3};\n"
        : "+f"(c[0]), "+f"(c[1]), "+f"(c[2]), "+f"(c[3])
        : "r"(a0), "r"(a1), "r"(a2), "r"(a3), "r"(b0), "r"(b1));
}

__device__ __forceinline__ void red_v4(float* p, float4 v) {
    asm volatile("red.global.add.v4.f32 [%0], {%1,%2,%3,%4};"
                 :: "l"(p), "f"(v.x), "f"(v.y), "f"(v.z), "f"(v.w)
                 : "memory");
}

// ---------------------------------------------------------------------------
// Scatter phase, 128-feature rows (F4=32): warp = one edge row (512B),
// 4 edges per iteration, gathers batched for MLP.
// ---------------------------------------------------------------------------
template <bool FEAT_CG>
__device__ void scatter128_phase(const float* __restrict__ feat,
                                 const int* __restrict__ ei,
                                 float* __restrict__ agg) {
    const int lane = threadIdx.x & 31;
    const int gwarp = blockIdx.x * NWARP + (threadIdx.x >> 5);
    const float4* f4 = (const float4*)feat;

    for (int e0 = gwarp * 4; e0 < E_EDGES; e0 += TOTWARPS * 4) {
        int s0 = __ldg(ei + e0 + 0), s1 = __ldg(ei + e0 + 1);
        int s2 = __ldg(ei + e0 + 2), s3 = __ldg(ei + e0 + 3);
        int d0 = __ldg(ei + E_EDGES + e0 + 0), d1 = __ldg(ei + E_EDGES + e0 + 1);
        int d2 = __ldg(ei + E_EDGES + e0 + 2), d3 = __ldg(ei + E_EDGES + e0 + 3);
        const float4* p0 = f4 + (long long)s0 * 32 + lane;
        const float4* p1 = f4 + (long long)s1 * 32 + lane;
        const float4* p2 = f4 + (long long)s2 * 32 + lane;
        const float4* p3 = f4 + (long long)s3 * 32 + lane;
        float4 v0 = FEAT_CG ? __ldcg(p0) : __ldg(p0);
        float4 v1 = FEAT_CG ? __ldcg(p1) : __ldg(p1);
        float4 v2 = FEAT_CG ? __ldcg(p2) : __ldg(p2);
        float4 v3 = FEAT_CG ? __ldcg(p3) : __ldg(p3);
        red_v4(agg + ((long long)d0 * 32 + lane) * 4, v0);
        red_v4(agg + ((long long)d1 * 32 + lane) * 4, v1);
        red_v4(agg + ((long long)d2 * 32 + lane) * 4, v2);
        red_v4(agg + ((long long)d3 * 32 + lane) * 4, v3);
    }
}

// ---------------------------------------------------------------------------
// Scatter phase, 64-feature rows (F4=16): half-warp = one edge row (256B),
// 8 edges per warp-iteration (2 per unroll step).
// ---------------------------------------------------------------------------
template <bool FEAT_CG>
__device__ void scatter64_phase(const float* __restrict__ feat,
                                const int* __restrict__ ei,
                                float* __restrict__ agg) {
    const int lane = threadIdx.x & 31;
    const int c    = lane & 15;        // float4 index within row
    const int sub  = lane >> 4;        // 0/1: which edge of the pair
    const int gwarp = blockIdx.x * NWARP + (threadIdx.x >> 5);
    const float4* f4 = (const float4*)feat;

    for (int e0 = gwarp * 8; e0 < E_EDGES; e0 += TOTWARPS * 8) {
        int ea = e0 + sub;             // this half-warp's edges: ea, ea+2, ea+4, ea+6
        int s0 = __ldg(ei + ea + 0), s1 = __ldg(ei + ea + 2);
        int s2 = __ldg(ei + ea + 4), s3 = __ldg(ei + ea + 6);
        int d0 = __ldg(ei + E_EDGES + ea + 0), d1 = __ldg(ei + E_EDGES + ea + 2);
        int d2 = __ldg(ei + E_EDGES + ea + 4), d3 = __ldg(ei + E_EDGES + ea + 6);
        const float4* p0 = f4 + (long long)s0 * 16 + c;
        const float4* p1 = f4 + (long long)s1 * 16 + c;
        const float4* p2 = f4 + (long long)s2 * 16 + c;
        const float4* p3 = f4 + (long long)s3 * 16 + c;
        float4 v0 = FEAT_CG ? __ldcg(p0) : __ldg(p0);
        float4 v1 = FEAT_CG ? __ldcg(p1) : __ldg(p1);
        float4 v2 = FEAT_CG ? __ldcg(p2) : __ldg(p2);
        float4 v3 = FEAT_CG ? __ldcg(p3) : __ldg(p3);
        red_v4(agg + ((long long)d0 * 16 + c) * 4, v0);
        red_v4(agg + ((long long)d1 * 16 + c) * 4, v1);
        red_v4(agg + ((long long)d2 * 16 + c) * 4, v2);
        red_v4(agg + ((long long)d3 * 16 + c) * 4, v3);
    }
}

// ---------------------------------------------------------------------------
// TF32 tensor-core GEMM phase:
//   out[node,128] = [A_row ; B_row] @ [Wrel ; Wroot]^T + bias  (opt. ELU)
// Tile = 64 nodes x 128 outs; 16 warps in 4x4 grid of m16n32 warp-tiles.
// ---------------------------------------------------------------------------
template <int K, bool DO_ELU, bool A_CG, bool B_CG>
__device__ void gemm_mma_phase(const float* __restrict__ A,
                               const float* __restrict__ B,
                               const float* __restrict__ Wrel,
                               const float* __restrict__ Wroot,
                               const float* __restrict__ bias,
                               float* __restrict__ out, float* sm) {
    constexpr int HALF = K / 2;
    constexpr int WROW = 136;       // padded weight row (floats)
    constexpr int SROW = K + 4;     // padded staging row (floats)
    uint32_t* Wt = (uint32_t*)sm;                // [K][WROW] tf32
    uint32_t* S  = (uint32_t*)(sm + K * WROW);   // [64][SROW] tf32

    for (int idx = threadIdx.x; idx < (K / 4) * 128; idx += TPB) {
        int i4 = idx % (K / 4);
        int j  = idx / (K / 4);
        int k0 = i4 * 4;
        float4 v = (k0 < HALF)
            ? *(const float4*)(Wrel  + j * HALF + k0)
            : *(const float4*)(Wroot + j * HALF + (k0 - HALF));
        Wt[(k0 + 0) * WROW + j] = f2tf32(v.x);
        Wt[(k0 + 1) * WROW + j] = f2tf32(v.y);
        Wt[(k0 + 2) * WROW + j] = f2tf32(v.z);
        Wt[(k0 + 3) * WROW + j] = f2tf32(v.w);
    }

    const int lane = threadIdx.x & 31;
    const int warp = threadIdx.x >> 5;
    const int mw = warp >> 2;       // 0..3 : node-row group
    const int nw = warp & 3;        // 0..3 : output-col group
    const int g  = lane >> 2;       // groupID 0..7
    const int tg = lane & 3;        // threadID_in_group 0..3

    for (int tile = blockIdx.x * 64; tile < N_NODES; tile += GRID * 64) {
        __syncthreads();   // prior iter's mma reads done; weights ready (1st)
        for (int idx = threadIdx.x; idx < 64 * (K / 4); idx += TPB) {
            int k4 = idx % (K / 4);
            int nl = idx / (K / 4);
            int node = tile + nl;
            float4 v = make_float4(0.f, 0.f, 0.f, 0.f);
            if (node < N_NODES) {
                if (k4 < HALF / 4) {
                    const float4* ap = ((const float4*)A) + (long long)node * (HALF / 4) + k4;
                    v = A_CG ? __ldcg(ap) : __ldg(ap);
                } else {
                    const float4* bp = ((const float4*)B) + (long long)node * (HALF / 4) + (k4 - HALF / 4);
                    v = B_CG ? __ldcg(bp) : __ldg(bp);
                }
            }
            uint4 t;
            t.x = f2tf32(v.x); t.y = f2tf32(v.y);
            t.z = f2tf32(v.z); t.w = f2tf32(v.w);
            *(uint4*)&S[nl * SROW + k4 * 4] = t;
        }
        __syncthreads();

        float c[4][4] = {};
        const int arow0 = (mw * 16 + g) * SROW;
        const int arow8 = arow0 + 8 * SROW;
        #pragma unroll 4
        for (int kk = 0; kk < K; kk += 8) {
            uint32_t a0 = S[arow0 + kk + tg];
            uint32_t a1 = S[arow8 + kk + tg];
            uint32_t a2 = S[arow0 + kk + tg + 4];
            uint32_t a3 = S[arow8 + kk + tg + 4];
            #pragma unroll
            for (int j = 0; j < 4; j++) {
                int n0 = nw * 32 + j * 8 + g;
                uint32_t b0 = Wt[(kk + tg) * WROW + n0];
                uint32_t b1 = Wt[(kk + 4 + tg) * WROW + n0];
                mma_tf32(c[j], a0, a1, a2, a3, b0, b1);
            }
        }

        int r0 = tile + mw * 16 + g;
        int r1 = r0 + 8;
        #pragma unroll
        for (int j = 0; j < 4; j++) {
            int col = nw * 32 + j * 8 + tg * 2;
            float bx = __ldg(bias + col);
            float by = __ldg(bias + col + 1);
            if (r0 < N_NODES) {
                float ox = c[j][0] + bx, oy = c[j][1] + by;
                if (DO_ELU) { ox = eluf(ox); oy = eluf(oy); }
                *(float2*)&out[(long long)r0 * 128 + col] = make_float2(ox, oy);
            }
            if (r1 < N_NODES) {
                float ox = c[j][2] + bx, oy = c[j][3] + by;
                if (DO_ELU) { ox = eluf(ox); oy = eluf(oy); }
                *(float2*)&out[(long long)r1 * 128 + col] = make_float2(ox, oy);
            }
        }
    }
    __syncthreads();
}

// ---------------------------------------------------------------------------
// FC head phase: out[n] = relu(h2[n] @ Wfc1^T + b1) @ Wfc2^T + b2
// ---------------------------------------------------------------------------
__device__ void fc_phase(const float* __restrict__ h2,
                         const float* __restrict__ Wfc1,
                         const float* __restrict__ bfc1,
                         const float* __restrict__ Wfc2,
                         const float* __restrict__ bfc2,
                         float* __restrict__ out, float* sm, int gtid) {
    float* W1s = sm;            // 20*128
    float* W2s = sm + 2560;     // 20
    float* b1s = sm + 2580;     // 20
    for (int i = threadIdx.x; i < 20 * 128; i += TPB) W1s[i] = Wfc1[i];
    if (threadIdx.x < 20) {
        W2s[threadIdx.x] = Wfc2[threadIdx.x];
        b1s[threadIdx.x] = bfc1[threadIdx.x];
    }
    __syncthreads();
    const float b2 = bfc2[0];

    for (int node = gtid; node < N_NODES; node += GSTR) {
        const float4* r = (const float4*)(h2 + (long long)node * 128);
        float acc[20];
        #pragma unroll
        for (int k = 0; k < 20; k++) acc[k] = b1s[k];
        #pragma unroll 4
        for (int i4 = 0; i4 < 32; i4++) {
            float4 v = __ldcg(r + i4);
            #pragma unroll
            for (int k = 0; k < 20; k++) {
                const float* w = &W1s[k * 128 + i4 * 4];
                acc[k] += v.x * w[0] + v.y * w[1] + v.z * w[2] + v.w * w[3];
            }
        }
        float o = b2;
        #pragma unroll
        for (int k = 0; k < 20; k++) o += fmaxf(acc[k], 0.f) * W2s[k];
        out[node] = o;
    }
}

// ---------------------------------------------------------------------------
// Single fused kernel: the entire network, one launch, pure function of inputs.
// ---------------------------------------------------------------------------
__global__ void __launch_bounds__(TPB, 1)
fused_gcn(const float* __restrict__ x, const int* __restrict__ ei,
          const float* __restrict__ W1_rel, const float* __restrict__ b1,
          const float* __restrict__ W1_root,
          const float* __restrict__ W2_rel, const float* __restrict__ b2,
          const float* __restrict__ W2_root,
          const float* __restrict__ Wfc1, const float* __restrict__ bfc1,
          const float* __restrict__ Wfc2, const float* __restrict__ bfc2,
          float* __restrict__ out) {
    extern __shared__ float sm[];
    const int gtid = blockIdx.x * TPB + threadIdx.x;

    // Phase 0: zero accumulators
    {
        const float4 z = make_float4(0.f, 0.f, 0.f, 0.f);
        float4* a1 = (float4*)g_agg1;
        float4* a2 = (float4*)g_agg2;
        for (int i = gtid; i < N_NODES * 64 / 4;  i += GSTR) a1[i] = z;
        for (int i = gtid; i < N_NODES * 128 / 4; i += GSTR) a2[i] = z;
    }
    grid_barrier();

    // Phase 1: agg1[dst] += x[src]  (64 feats, half-warp per edge)
    scatter64_phase<false>(x, ei, g_agg1);
    grid_barrier();

    // Phase 2: h = elu(agg1 @ W1_rel^T + b1 + x @ W1_root^T)  [TF32 mma]
    gemm_mma_phase<128, true, true, false>(g_agg1, x, W1_rel, W1_root, b1, g_h, sm);
    grid_barrier();

    // Phase 3: agg2[dst] += h[src]  (128 feats, warp per edge)
    scatter128_phase<true>(g_h, ei, g_agg2);
    grid_barrier();

    // Phase 4: h2 = agg2 @ W2_rel^T + b2 + h @ W2_root^T  [TF32 mma]
    gemm_mma_phase<256, false, true, true>(g_agg2, g_h, W2_rel, W2_root, b2, g_h2, sm);
    grid_barrier();

    // Phase 5: out = relu(h2 @ Wfc1^T + bfc1) @ Wfc2^T + bfc2
    fc_phase(g_h2, Wfc1, bfc1, Wfc2, bfc2, out, sm, gtid);
}

// ---------------------------------------------------------------------------
extern "C" void kernel_launch(void* const* d_in, const int* in_sizes, int n_in,
                              void* d_out, int out_size) {
    const float* x       = (const float*)d_in[0];
    const int*   ei      = (const int*)d_in[1];
    const float* W1_rel  = (const float*)d_in[2];
    const float* b1      = (const float*)d_in[3];
    const float* W1_root = (const float*)d_in[4];
    const float* W2_rel  = (const float*)d_in[5];
    const float* b2      = (const float*)d_in[6];
    const float* W2_root = (const float*)d_in[7];
    const float* Wfc1    = (const float*)d_in[8];
    const float* bfc1    = (const float*)d_in[9];
    const float* Wfc2    = (const float*)d_in[10];
    const float* bfc2    = (const float*)d_in[11];
    float* out = (float*)d_out;

    // smem: max over phases = K=256 gemm: 256*136 + 64*260 floats = 205824 B
    const int smem = (256 * 136 + 64 * 260) * 4;
    cudaFuncSetAttribute(fused_gcn,
                         cudaFuncAttributeMaxDynamicSharedMemorySize, smem);

    fused_gcn<<<GRID, TPB, smem>>>(x, ei, W1_rel, b1, W1_root,
                                   W2_rel, b2, W2_root,
                                   Wfc1, bfc1, Wfc2, bfc2, out);
}

// round 15
// speedup vs baseline: 1.9957x; 1.0299x over previous
#include <cuda_runtime.h>
#include <cstdint>

#define N_NODES 100000
#define E_EDGES 800000
#define GRID    148
#define TPB     1024
#define NWARP   (TPB / 32)
#define GSTR    (GRID * TPB)
#define TOTWARPS (GRID * NWARP)

// Scratch (device globals). The fused kernel zeroes its own accumulators in
// phase 0 of EVERY launch; pure function of inputs (mod atomic fp ordering).
__device__ float g_agg1[N_NODES * 64];
__device__ float g_h   [N_NODES * 128];
__device__ float g_agg2[N_NODES * 128];
__device__ float g_h2  [N_NODES * 128];

// Software grid barrier (grid == #SMs, 1 CTA/SM -> all co-resident).
__device__ unsigned g_bar_arrive;
__device__ unsigned g_bar_gen;

__device__ __forceinline__ void grid_barrier() {
    __syncthreads();
    if (threadIdx.x == 0) {
        __threadfence();
        unsigned gen = atomicAdd(&g_bar_gen, 0u);
        unsigned ticket = atomicAdd(&g_bar_arrive, 1u);
        if (ticket == GRID - 1) {
            atomicExch(&g_bar_arrive, 0u);
            __threadfence();
            atomicAdd(&g_bar_gen, 1u);
        } else {
            while (atomicAdd(&g_bar_gen, 0u) == gen) { __nanosleep(64); }
        }
        __threadfence();
    }
    __syncthreads();
}

__device__ __forceinline__ float eluf(float v) {
    return v > 0.f ? v : expm1f(v);
}

__device__ __forceinline__ uint32_t f2tf32(float f) {
    uint32_t u;
    asm("cvt.rna.tf32.f32 %0, %1;" : "=r"(u) : "f"(f));
    return u;
}

__device__ __forceinline__ void mma_tf32(float c[4], uint32_t a0, uint32_t a1,
                                         uint32_t a2, uint32_t a3,
                                         uint32_t b0, uint32_t b1) {
    asm volatile(
        "mma.sync.aligned.m16n8k8.row.col.f32.tf32.tf32.f32 "
        "{%0,%1,%2,%3}, {%4,%5,%6,%7}, {%8,%9}, {%0,%1,%2,%3};\n"
        : "+f"(c[0]), "+f"(c[1]), "+f"(c[2]), "+f"(c[3])
        : "r"(a0), "r"(a1), "r"(a2), "r"(a3), "r"(b0), "r"(b1));
}

__device__ __forceinline__ void red_v4(float* p, float4 v) {
    asm volatile("red.global.add.v4.f32 [%0], {%1,%2,%3,%4};"
                 :: "l"(p), "f"(v.x), "f"(v.y), "f"(v.z), "f"(v.w)
                 : "memory");
}

// ---------------------------------------------------------------------------
// Scatter phase, 128-feature rows (F4=32): warp = one edge row (512B),
// 4 edges per iteration, gathers batched for MLP.
// ---------------------------------------------------------------------------
template <bool FEAT_CG>
__device__ void scatter128_phase(const float* __restrict__ feat,
                                 const int* __restrict__ ei,
                                 float* __restrict__ agg) {
    const int lane = threadIdx.x & 31;
    const int gwarp = blockIdx.x * NWARP + (threadIdx.x >> 5);
    const float4* f4 = (const float4*)feat;

    for (int e0 = gwarp * 4; e0 < E_EDGES; e0 += TOTWARPS * 4) {
        int s0 = __ldg(ei + e0 + 0), s1 = __ldg(ei + e0 + 1);
        int s2 = __ldg(ei + e0 + 2), s3 = __ldg(ei + e0 + 3);
        int d0 = __ldg(ei + E_EDGES + e0 + 0), d1 = __ldg(ei + E_EDGES + e0 + 1);
        int d2 = __ldg(ei + E_EDGES + e0 + 2), d3 = __ldg(ei + E_EDGES + e0 + 3);
        const float4* p0 = f4 + (long long)s0 * 32 + lane;
        const float4* p1 = f4 + (long long)s1 * 32 + lane;
        const float4* p2 = f4 + (long long)s2 * 32 + lane;
        const float4* p3 = f4 + (long long)s3 * 32 + lane;
        float4 v0 = FEAT_CG ? __ldcg(p0) : __ldg(p0);
        float4 v1 = FEAT_CG ? __ldcg(p1) : __ldg(p1);
        float4 v2 = FEAT_CG ? __ldcg(p2) : __ldg(p2);
        float4 v3 = FEAT_CG ? __ldcg(p3) : __ldg(p3);
        red_v4(agg + ((long long)d0 * 32 + lane) * 4, v0);
        red_v4(agg + ((long long)d1 * 32 + lane) * 4, v1);
        red_v4(agg + ((long long)d2 * 32 + lane) * 4, v2);
        red_v4(agg + ((long long)d3 * 32 + lane) * 4, v3);
    }
}

// ---------------------------------------------------------------------------
// Scatter phase, 64-feature rows (F4=16): half-warp = one edge row (256B),
// 8 edges per warp-iteration.
// ---------------------------------------------------------------------------
template <bool FEAT_CG>
__device__ void scatter64_phase(const float* __restrict__ feat,
                                const int* __restrict__ ei,
                                float* __restrict__ agg) {
    const int lane = threadIdx.x & 31;
    const int c    = lane & 15;        // float4 index within row
    const int sub  = lane >> 4;        // 0/1: which edge of the pair
    const int gwarp = blockIdx.x * NWARP + (threadIdx.x >> 5);
    const float4* f4 = (const float4*)feat;

    for (int e0 = gwarp * 8; e0 < E_EDGES; e0 += TOTWARPS * 8) {
        int ea = e0 + sub;             // this half-warp's edges: ea, ea+2, ea+4, ea+6
        int s0 = __ldg(ei + ea + 0), s1 = __ldg(ei + ea + 2);
        int s2 = __ldg(ei + ea + 4), s3 = __ldg(ei + ea + 6);
        int d0 = __ldg(ei + E_EDGES + ea + 0), d1 = __ldg(ei + E_EDGES + ea + 2);
        int d2 = __ldg(ei + E_EDGES + ea + 4), d3 = __ldg(ei + E_EDGES + ea + 6);
        const float4* p0 = f4 + (long long)s0 * 16 + c;
        const float4* p1 = f4 + (long long)s1 * 16 + c;
        const float4* p2 = f4 + (long long)s2 * 16 + c;
        const float4* p3 = f4 + (long long)s3 * 16 + c;
        float4 v0 = FEAT_CG ? __ldcg(p0) : __ldg(p0);
        float4 v1 = FEAT_CG ? __ldcg(p1) : __ldg(p1);
        float4 v2 = FEAT_CG ? __ldcg(p2) : __ldg(p2);
        float4 v3 = FEAT_CG ? __ldcg(p3) : __ldg(p3);
        red_v4(agg + ((long long)d0 * 16 + c) * 4, v0);
        red_v4(agg + ((long long)d1 * 16 + c) * 4, v1);
        red_v4(agg + ((long long)d2 * 16 + c) * 4, v2);
        red_v4(agg + ((long long)d3 * 16 + c) * 4, v3);
    }
}

// ---------------------------------------------------------------------------
// TF32 tensor-core GEMM phase:
//   out[node,128] = [A_row ; B_row] @ [Wrel ; Wroot]^T + bias  (opt. ELU)
// Tile = 64 nodes x 128 outs; 32 warps in 4x8 grid of m16n16 warp-tiles
// (8 accum regs/thread -> fits the 64-reg cap at 1024 threads).
// ---------------------------------------------------------------------------
template <int K, bool DO_ELU, bool A_CG, bool B_CG>
__device__ void gemm_mma_phase(const float* __restrict__ A,
                               const float* __restrict__ B,
                               const float* __restrict__ Wrel,
                               const float* __restrict__ Wroot,
                               const float* __restrict__ bias,
                               float* __restrict__ out, float* sm) {
    constexpr int HALF = K / 2;
    constexpr int WROW = 136;       // padded weight row (floats)
    constexpr int SROW = K + 4;     // padded staging row (floats)
    uint32_t* Wt = (uint32_t*)sm;                // [K][WROW] tf32
    uint32_t* S  = (uint32_t*)(sm + K * WROW);   // [64][SROW] tf32

    for (int idx = threadIdx.x; idx < (K / 4) * 128; idx += TPB) {
        int i4 = idx % (K / 4);
        int j  = idx / (K / 4);
        int k0 = i4 * 4;
        float4 v = (k0 < HALF)
            ? *(const float4*)(Wrel  + j * HALF + k0)
            : *(const float4*)(Wroot + j * HALF + (k0 - HALF));
        Wt[(k0 + 0) * WROW + j] = f2tf32(v.x);
        Wt[(k0 + 1) * WROW + j] = f2tf32(v.y);
        Wt[(k0 + 2) * WROW + j] = f2tf32(v.z);
        Wt[(k0 + 3) * WROW + j] = f2tf32(v.w);
    }

    const int lane = threadIdx.x & 31;
    const int warp = threadIdx.x >> 5;
    const int mw = warp >> 3;       // 0..3 : node-row group (16 rows each)
    const int nw = warp & 7;        // 0..7 : output-col group (16 cols each)
    const int g  = lane >> 2;       // groupID 0..7
    const int tg = lane & 3;        // threadID_in_group 0..3

    for (int tile = blockIdx.x * 64; tile < N_NODES; tile += GRID * 64) {
        __syncthreads();   // prior iter's mma reads done; weights ready (1st)
        for (int idx = threadIdx.x; idx < 64 * (K / 4); idx += TPB) {
            int k4 = idx % (K / 4);
            int nl = idx / (K / 4);
            int node = tile + nl;
            float4 v = make_float4(0.f, 0.f, 0.f, 0.f);
            if (node < N_NODES) {
                if (k4 < HALF / 4) {
                    const float4* ap = ((const float4*)A) + (long long)node * (HALF / 4) + k4;
                    v = A_CG ? __ldcg(ap) : __ldg(ap);
                } else {
                    const float4* bp = ((const float4*)B) + (long long)node * (HALF / 4) + (k4 - HALF / 4);
                    v = B_CG ? __ldcg(bp) : __ldg(bp);
                }
            }
            uint4 t;
            t.x = f2tf32(v.x); t.y = f2tf32(v.y);
            t.z = f2tf32(v.z); t.w = f2tf32(v.w);
            *(uint4*)&S[nl * SROW + k4 * 4] = t;
        }
        __syncthreads();

        float c[2][4] = {};
        const int arow0 = (mw * 16 + g) * SROW;
        const int arow8 = arow0 + 8 * SROW;
        #pragma unroll 4
        for (int kk = 0; kk < K; kk += 8) {
            uint32_t a0 = S[arow0 + kk + tg];
            uint32_t a1 = S[arow8 + kk + tg];
            uint32_t a2 = S[arow0 + kk + tg + 4];
            uint32_t a3 = S[arow8 + kk + tg + 4];
            #pragma unroll
            for (int j = 0; j < 2; j++) {
                int n0 = nw * 16 + j * 8 + g;
                uint32_t b0 = Wt[(kk + tg) * WROW + n0];
                uint32_t b1 = Wt[(kk + 4 + tg) * WROW + n0];
                mma_tf32(c[j], a0, a1, a2, a3, b0, b1);
            }
        }

        int r0 = tile + mw * 16 + g;
        int r1 = r0 + 8;
        #pragma unroll
        for (int j = 0; j < 2; j++) {
            int col = nw * 16 + j * 8 + tg * 2;
            float bx = __ldg(bias + col);
            float by = __ldg(bias + col + 1);
            if (r0 < N_NODES) {
                float ox = c[j][0] + bx, oy = c[j][1] + by;
                if (DO_ELU) { ox = eluf(ox); oy = eluf(oy); }
                *(float2*)&out[(long long)r0 * 128 + col] = make_float2(ox, oy);
            }
            if (r1 < N_NODES) {
                float ox = c[j][2] + bx, oy = c[j][3] + by;
                if (DO_ELU) { ox = eluf(ox); oy = eluf(oy); }
                *(float2*)&out[(long long)r1 * 128 + col] = make_float2(ox, oy);
            }
        }
    }
    __syncthreads();
}

// ---------------------------------------------------------------------------
// FC head phase: out[n] = relu(h2[n] @ Wfc1^T + b1) @ Wfc2^T + b2
// ---------------------------------------------------------------------------
__device__ void fc_phase(const float* __restrict__ h2,
                         const float* __restrict__ Wfc1,
                         const float* __restrict__ bfc1,
                         const float* __restrict__ Wfc2,
                         const float* __restrict__ bfc2,
                         float* __restrict__ out, float* sm, int gtid) {
    float* W1s = sm;            // 20*128
    float* W2s = sm + 2560;     // 20
    float* b1s = sm + 2580;     // 20
    for (int i = threadIdx.x; i < 20 * 128; i += TPB) W1s[i] = Wfc1[i];
    if (threadIdx.x < 20) {
        W2s[threadIdx.x] = Wfc2[threadIdx.x];
        b1s[threadIdx.x] = bfc1[threadIdx.x];
    }
    __syncthreads();
    const float b2 = bfc2[0];

    for (int node = gtid; node < N_NODES; node += GSTR) {
        const float4* r = (const float4*)(h2 + (long long)node * 128);
        float acc[20];
        #pragma unroll
        for (int k = 0; k < 20; k++) acc[k] = b1s[k];
        #pragma unroll 4
        for (int i4 = 0; i4 < 32; i4++) {
            float4 v = __ldcg(r + i4);
            #pragma unroll
            for (int k = 0; k < 20; k++) {
                const float* w = &W1s[k * 128 + i4 * 4];
                acc[k] += v.x * w[0] + v.y * w[1] + v.z * w[2] + v.w * w[3];
            }
        }
        float o = b2;
        #pragma unroll
        for (int k = 0; k < 20; k++) o += fmaxf(acc[k], 0.f) * W2s[k];
        out[node] = o;
    }
}

// ---------------------------------------------------------------------------
// Single fused kernel: the entire network, one launch, pure function of inputs.
// ---------------------------------------------------------------------------
__global__ void __launch_bounds__(TPB, 1)
fused_gcn(const float* __restrict__ x, const int* __restrict__ ei,
          const float* __restrict__ W1_rel, const float* __restrict__ b1,
          const float* __restrict__ W1_root,
          const float* __restrict__ W2_rel, const float* __restrict__ b2,
          const float* __restrict__ W2_root,
          const float* __restrict__ Wfc1, const float* __restrict__ bfc1,
          const float* __restrict__ Wfc2, const float* __restrict__ bfc2,
          float* __restrict__ out) {
    extern __shared__ float sm[];
    const int gtid = blockIdx.x * TPB + threadIdx.x;

    // Phase 0: zero accumulators
    {
        const float4 z = make_float4(0.f, 0.f, 0.f, 0.f);
        float4* a1 = (float4*)g_agg1;
        float4* a2 = (float4*)g_agg2;
        for (int i = gtid; i < N_NODES * 64 / 4;  i += GSTR) a1[i] = z;
        for (int i = gtid; i < N_NODES * 128 / 4; i += GSTR) a2[i] = z;
    }
    grid_barrier();

    // Phase 1: agg1[dst] += x[src]  (64 feats, half-warp per edge)
    scatter64_phase<false>(x, ei, g_agg1);
    grid_barrier();

    // Phase 2: h = elu(agg1 @ W1_rel^T + b1 + x @ W1_root^T)  [TF32 mma]
    gemm_mma_phase<128, true, true, false>(g_agg1, x, W1_rel, W1_root, b1, g_h, sm);
    grid_barrier();

    // Phase 3: agg2[dst] += h[src]  (128 feats, warp per edge)
    scatter128_phase<true>(g_h, ei, g_agg2);
    grid_barrier();

    // Phase 4: h2 = agg2 @ W2_rel^T + b2 + h @ W2_root^T  [TF32 mma]
    gemm_mma_phase<256, false, true, true>(g_agg2, g_h, W2_rel, W2_root, b2, g_h2, sm);
    grid_barrier();

    // Phase 5: out = relu(h2 @ Wfc1^T + bfc1) @ Wfc2^T + bfc2
    fc_phase(g_h2, Wfc1, bfc1, Wfc2, bfc2, out, sm, gtid);
}

// ---------------------------------------------------------------------------
extern "C" void kernel_launch(void* const* d_in, const int* in_sizes, int n_in,
                              void* d_out, int out_size) {
    const float* x       = (const float*)d_in[0];
    const int*   ei      = (const int*)d_in[1];
    const float* W1_rel  = (const float*)d_in[2];
    const float* b1      = (const float*)d_in[3];
    const float* W1_root = (const float*)d_in[4];
    const float* W2_rel  = (const float*)d_in[5];
    const float* b2      = (const float*)d_in[6];
    const float* W2_root = (const float*)d_in[7];
    const float* Wfc1    = (const float*)d_in[8];
    const float* bfc1    = (const float*)d_in[9];
    const float* Wfc2    = (const float*)d_in[10];
    const float* bfc2    = (const float*)d_in[11];
    float* out = (float*)d_out;

    // smem: max over phases = K=256 gemm: 256*136 + 64*260 floats = 205824 B
    const int smem = (256 * 136 + 64 * 260) * 4;
    cudaFuncSetAttribute(fused_gcn,
                         cudaFuncAttributeMaxDynamicSharedMemorySize, smem);

    fused_gcn<<<GRID, TPB, smem>>>(x, ei, W1_rel, b1, W1_root,
                                   W2_rel, b2, W2_root,
                                   Wfc1, bfc1, Wfc2, bfc2, out);
}